// round 2
// baseline (speedup 1.0000x reference)
#include <cuda_runtime.h>
#include <cuda_bf16.h>

#define BLK 256
#define NB  10

// FC = 1.14136 * e^2 * sqrt(10)  (smooth_finite coefficient * NUM_BASIS^0.5)
#define FC_CONST 26.6692997f
#define SQRT3_F  1.7320508075688772f

__global__ void __launch_bounds__(BLK) qsh_kernel(
    const float* __restrict__ pos,     // [100000,3]
    const float* __restrict__ qpos,    // [10000,3] (query_pos flattened)
    const int*   __restrict__ esrc,    // [E] -> qpos rows
    const int*   __restrict__ edst,    // [E] -> pos rows
    float*       __restrict__ out,     // [E*9] sh | [E*10] embed
    int E)
{
    __shared__ float s_sh [BLK * 9];
    __shared__ float s_emb[BLK * NB];

    const int t = threadIdx.x;
    const long long e = (long long)blockIdx.x * BLK + t;

    float vx = 0.f, vy = 0.f, vz = 0.f;
    if (e < (long long)E) {
        const int si = esrc[e];
        const int di = edst[e];
        // gather: qpos rows live in ~120KB (L1/L2 resident), pos in 1.2MB (L2 resident)
        vx = qpos[si * 3 + 0] - pos[di * 3 + 0];
        vy = qpos[si * 3 + 1] - pos[di * 3 + 1];
        vz = qpos[si * 3 + 2] - pos[di * 3 + 2];
    }

    const float s2   = vx * vx + vy * vy + vz * vz;
    const float rinv = (s2 > 0.f) ? rsqrtf(s2) : 0.f;
    const float r    = s2 * rinv;               // == sqrt(s2), 0 when s2==0
    const float x = vx * rinv, y = vy * rinv, z = vz * rinv;

    // ---- spherical harmonics (lmax=2, e3nn norm) into SMEM tile ----
    // stride 9 is coprime to 32 banks -> conflict-free per-instruction
    float* msh = s_sh + t * 9;
    msh[0] = 1.f;
    msh[1] = x;
    msh[2] = y;
    msh[3] = z;
    msh[4] = SQRT3_F * x * z;
    msh[5] = SQRT3_F * x * y;
    msh[6] = y * y - 0.5f * (x * x + z * z);
    msh[7] = SQRT3_F * y * z;
    msh[8] = 0.5f * SQRT3_F * (z * z - x * x);

    // ---- smooth finite embed: at most 2 of 10 basis fns are nonzero ----
    // values[j] = (j+1)/11, step = 1/11, d_j = 11*r - (j+1), nonzero iff |d_j|<1
    // sus(1+d)*sus(1-d) = exp(-2/(1-d^2))
    float* memb = s_emb + t * NB;
    #pragma unroll
    for (int j = 0; j < NB; j++) memb[j] = 0.f;

    const float tt = r * 11.0f;
    const int   k  = (int)tt;                    // floor (tt >= 0)
    const float d1 = tt - (float)k;              // in [0,1): candidate j = k-1
    if (k >= 1 && k <= NB) {
        memb[k - 1] = FC_CONST * __expf(-2.f / (1.f - d1 * d1));
    }
    const float d2 = d1 - 1.f;                   // in [-1,0): candidate j = k
    if (k < NB && d2 > -1.f) {
        memb[k] = FC_CONST * __expf(-2.f / (1.f - d2 * d2));
    }

    __syncthreads();

    // ---- coalesced drain: SMEM tiles -> global, float4 STG.128 ----
    const long long blockBase = (long long)blockIdx.x * BLK;
    const int nval = (int)min((long long)BLK, (long long)E - blockBase);
    float* out_sh  = out;
    float* out_emb = out + (long long)E * 9;

    if (nval == BLK) {
        // 9*BLK = 2304 floats = 576 float4; base byte offset blockBase*36 (16B-aligned: 256*36=9216)
        float4*       g4s = (float4*)(out_sh + blockBase * 9);
        const float4* s4s = (const float4*)s_sh;
        #pragma unroll
        for (int i = t; i < (BLK * 9) / 4; i += BLK) g4s[i] = s4s[i];

        // 10*BLK = 2560 floats = 640 float4; base byte offset blockBase*40 (16B-aligned)
        float4*       g4e = (float4*)(out_emb + blockBase * NB);
        const float4* s4e = (const float4*)s_emb;
        #pragma unroll
        for (int i = t; i < (BLK * NB) / 4; i += BLK) g4e[i] = s4e[i];
    } else {
        for (int i = t; i < nval * 9;  i += BLK) out_sh [blockBase * 9  + i] = s_sh [i];
        for (int i = t; i < nval * NB; i += BLK) out_emb[blockBase * NB + i] = s_emb[i];
    }
}

extern "C" void kernel_launch(void* const* d_in, const int* in_sizes, int n_in,
                              void* d_out, int out_size)
{
    const float* pos  = (const float*)d_in[0];
    const float* qpos = (const float*)d_in[1];
    const int*   esrc = (const int*)  d_in[2];
    const int*   edst = (const int*)  d_in[3];
    const int    E    = in_sizes[2];

    const int blocks = (E + BLK - 1) / BLK;
    qsh_kernel<<<blocks, BLK>>>(pos, qpos, esrc, edst, (float*)d_out, E);
}

// round 6
// speedup vs baseline: 1.1543x; 1.1543x over previous
#include <cuda_runtime.h>
#include <cuda_bf16.h>

#define BLK 256
#define NB  10

#define N_POS_MAX  100000
#define N_QPOS_MAX 10000

// FC = 1.14136 * e^2 * sqrt(10)
#define FC_CONST 26.6692997f
#define SQRT3_F  1.7320508075688772f

// Padded gather tables (16B rows -> single LDG.128 per gather).
// __device__ globals: no runtime allocation (harness rule).
__device__ float4 g_pos4 [N_POS_MAX];
__device__ float4 g_qpos4[N_QPOS_MAX];

__global__ void pad_tables_kernel(const float* __restrict__ pos,
                                  const float* __restrict__ qpos,
                                  int n_pos, int n_qpos)
{
    int i = blockIdx.x * blockDim.x + threadIdx.x;
    if (i < n_pos) {
        g_pos4[i] = make_float4(pos[3*i], pos[3*i+1], pos[3*i+2], 0.f);
    } else {
        int j = i - n_pos;
        if (j < n_qpos)
            g_qpos4[j] = make_float4(qpos[3*j], qpos[3*j+1], qpos[3*j+2], 0.f);
    }
}

__global__ void __launch_bounds__(BLK) qsh_kernel(
    const int* __restrict__ esrc,    // [E] -> qpos rows
    const int* __restrict__ edst,    // [E] -> pos rows
    float*     __restrict__ out,     // [E*9] sh | [E*10] embed
    int E)
{
    __shared__ float s_sh [BLK * 9];
    __shared__ float s_emb[BLK * NB];

    const int t = threadIdx.x;
    const long long e = (long long)blockIdx.x * BLK + t;

    // Vectorized zero-fill of the embed tile (640 float4 across 256 threads)
    {
        float4* z4 = (float4*)s_emb;
        #pragma unroll
        for (int i = t; i < (BLK * NB) / 4; i += BLK)
            z4[i] = make_float4(0.f, 0.f, 0.f, 0.f);
    }

    float vx = 0.f, vy = 0.f, vz = 0.f;
    if (e < (long long)E) {
        const int si = esrc[e];
        const int di = edst[e];
        const float4 a = __ldg(&g_qpos4[si]);   // 1x LDG.128 gather
        const float4 b = __ldg(&g_pos4[di]);    // 1x LDG.128 gather
        vx = a.x - b.x;
        vy = a.y - b.y;
        vz = a.z - b.z;
    }

    const float s2   = vx * vx + vy * vy + vz * vz;
    const float rinv = (s2 > 0.f) ? rsqrtf(s2) : 0.f;
    const float r    = s2 * rinv;               // == sqrt(s2), 0 when s2==0
    const float x = vx * rinv, y = vy * rinv, z = vz * rinv;

    __syncthreads();   // zero-fill visible to all before scatter

    // ---- spherical harmonics (lmax=2) into SMEM tile (stride 9: conflict-free)
    float* msh = s_sh + t * 9;
    msh[0] = 1.f;
    msh[1] = x;
    msh[2] = y;
    msh[3] = z;
    msh[4] = SQRT3_F * x * z;
    msh[5] = SQRT3_F * x * y;
    msh[6] = y * y - 0.5f * (x * x + z * z);
    msh[7] = SQRT3_F * y * z;
    msh[8] = 0.5f * SQRT3_F * (z * z - x * x);

    // ---- smooth finite embed: at most 2 of 10 basis fns nonzero ----
    // d_j = 11*r - (j+1), nonzero iff |d_j| < 1;
    // sus(1+d)*sus(1-d) = exp(-2/(1-d^2))
    float* memb = s_emb + t * NB;
    const float tt = r * 11.0f;
    const int   k  = (int)tt;                    // floor (tt >= 0)
    const float d1 = tt - (float)k;              // in [0,1): candidate j = k-1
    if (k >= 1 && k <= NB) {
        memb[k - 1] = FC_CONST * __expf(-2.f / (1.f - d1 * d1));
    }
    const float d2 = d1 - 1.f;                   // in [-1,0): candidate j = k
    if (k < NB && d2 > -1.f) {
        memb[k] = FC_CONST * __expf(-2.f / (1.f - d2 * d2));
    }

    __syncthreads();

    // ---- coalesced drain: SMEM tiles -> global, float4 STG.128 ----
    const long long blockBase = (long long)blockIdx.x * BLK;
    const int nval = (int)min((long long)BLK, (long long)E - blockBase);
    float* out_sh  = out;
    float* out_emb = out + (long long)E * 9;

    if (nval == BLK) {
        float4*       g4s = (float4*)(out_sh + blockBase * 9);
        const float4* s4s = (const float4*)s_sh;
        #pragma unroll
        for (int i = t; i < (BLK * 9) / 4; i += BLK) g4s[i] = s4s[i];

        float4*       g4e = (float4*)(out_emb + blockBase * NB);
        const float4* s4e = (const float4*)s_emb;
        #pragma unroll
        for (int i = t; i < (BLK * NB) / 4; i += BLK) g4e[i] = s4e[i];
    } else {
        for (int i = t; i < nval * 9;  i += BLK) out_sh [blockBase * 9  + i] = s_sh [i];
        for (int i = t; i < nval * NB; i += BLK) out_emb[blockBase * NB + i] = s_emb[i];
    }
}

extern "C" void kernel_launch(void* const* d_in, const int* in_sizes, int n_in,
                              void* d_out, int out_size)
{
    const float* pos  = (const float*)d_in[0];
    const float* qpos = (const float*)d_in[1];
    const int*   esrc = (const int*)  d_in[2];
    const int*   edst = (const int*)  d_in[3];

    const int n_pos  = in_sizes[0] / 3;
    const int n_qpos = in_sizes[1] / 3;
    const int E      = in_sizes[2];

    const int n_pad = n_pos + n_qpos;
    pad_tables_kernel<<<(n_pad + 255) / 256, 256>>>(pos, qpos, n_pos, n_qpos);

    const int blocks = (E + BLK - 1) / BLK;
    qsh_kernel<<<blocks, BLK>>>(esrc, edst, (float*)d_out, E);
}

// round 7
// speedup vs baseline: 1.1786x; 1.0211x over previous
#include <cuda_runtime.h>
#include <cuda_bf16.h>
#include <cstdint>

#define BLK 256
#define NB  10

#define N_POS_MAX  100000
#define N_QPOS_MAX 10000

// FC = 1.14136 * e^2 * sqrt(10)
#define FC_CONST 26.6692997f
#define SQRT3_F  1.7320508075688772f

// Padded gather tables (16B rows -> single LDG.128 per gather).
__device__ float4 g_pos4 [N_POS_MAX];
__device__ float4 g_qpos4[N_QPOS_MAX];

__global__ void pad_tables_kernel(const float* __restrict__ pos,
                                  const float* __restrict__ qpos,
                                  int n_pos, int n_qpos)
{
    int i = blockIdx.x * blockDim.x + threadIdx.x;
    if (i < n_pos) {
        g_pos4[i] = make_float4(pos[3*i], pos[3*i+1], pos[3*i+2], 0.f);
    } else {
        int j = i - n_pos;
        if (j < n_qpos)
            g_qpos4[j] = make_float4(qpos[3*j], qpos[3*j+1], qpos[3*j+2], 0.f);
    }
}

__device__ __forceinline__ uint32_t smem_u32(const void* p) {
    uint32_t a;
    asm("{ .reg .u64 t; cvta.to.shared.u64 t, %1; cvt.u32.u64 %0, t; }"
        : "=r"(a) : "l"(p));
    return a;
}

__global__ void __launch_bounds__(BLK) qsh_kernel(
    const int* __restrict__ esrc,    // [E] -> qpos rows
    const int* __restrict__ edst,    // [E] -> pos rows
    float*     __restrict__ out,     // [E*9] sh | [E*10] embed
    int E)
{
    __shared__ __align__(16) float s_sh [BLK * 9];
    __shared__ __align__(16) float s_emb[BLK * NB];

    const int t = threadIdx.x;
    const long long e = (long long)blockIdx.x * BLK + t;

    // Vectorized zero-fill of the embed tile
    {
        float4* z4 = (float4*)s_emb;
        #pragma unroll
        for (int i = t; i < (BLK * NB) / 4; i += BLK)
            z4[i] = make_float4(0.f, 0.f, 0.f, 0.f);
    }

    float vx = 0.f, vy = 0.f, vz = 0.f;
    if (e < (long long)E) {
        const int si = esrc[e];
        const int di = edst[e];
        const float4 a = __ldg(&g_qpos4[si]);   // 1x LDG.128 gather
        const float4 b = __ldg(&g_pos4[di]);    // 1x LDG.128 gather
        vx = a.x - b.x;
        vy = a.y - b.y;
        vz = a.z - b.z;
    }

    const float s2   = vx * vx + vy * vy + vz * vz;
    const float rinv = (s2 > 0.f) ? rsqrtf(s2) : 0.f;
    const float r    = s2 * rinv;               // == sqrt(s2), 0 when s2==0
    const float x = vx * rinv, y = vy * rinv, z = vz * rinv;

    __syncthreads();   // zero-fill visible before scatter

    // ---- spherical harmonics (lmax=2) into SMEM tile (stride 9: conflict-free)
    float* msh = s_sh + t * 9;
    msh[0] = 1.f;
    msh[1] = x;
    msh[2] = y;
    msh[3] = z;
    msh[4] = SQRT3_F * x * z;
    msh[5] = SQRT3_F * x * y;
    msh[6] = y * y - 0.5f * (x * x + z * z);
    msh[7] = SQRT3_F * y * z;
    msh[8] = 0.5f * SQRT3_F * (z * z - x * x);

    // ---- smooth finite embed: at most 2 of 10 basis fns nonzero ----
    // d_j = 11*r - (j+1), nonzero iff |d_j| < 1;
    // sus(1+d)*sus(1-d) = exp(-2/(1-d^2))
    float* memb = s_emb + t * NB;
    const float tt = r * 11.0f;
    const int   k  = (int)tt;                    // floor (tt >= 0)
    const float d1 = tt - (float)k;              // in [0,1): candidate j = k-1
    if (k >= 1 && k <= NB) {
        memb[k - 1] = FC_CONST * __expf(-2.f / (1.f - d1 * d1));
    }
    const float d2 = d1 - 1.f;                   // in [-1,0): candidate j = k
    if (k < NB && d2 > -1.f) {
        memb[k] = FC_CONST * __expf(-2.f / (1.f - d2 * d2));
    }

    __syncthreads();

    // ---- drain: SMEM tiles -> global ----
    const long long blockBase = (long long)blockIdx.x * BLK;
    const int nval = (int)min((long long)BLK, (long long)E - blockBase);
    float* out_sh  = out;
    float* out_emb = out + (long long)E * 9;

    // TMA bulk-store path: bypasses L1 entirely (SMEM -> L2 by the TMA engine).
    // Requires 16B-aligned global dst: sh dst offset = blockBase*36 (mult of 16
    // since blockBase mult of 256); emb dst = E*36 + blockBase*40 bytes, 16B-
    // aligned iff E % 4 == 0.
    const bool bulk_ok = (nval == BLK) && ((E & 3) == 0);
    if (bulk_ok) {
        if (t == 0) {
            asm volatile("fence.proxy.async.shared::cta;" ::: "memory");
            void* gsh = (void*)(out_sh  + blockBase * 9);
            void* gem = (void*)(out_emb + blockBase * NB);
            uint32_t ssh = smem_u32(s_sh);
            uint32_t sem = smem_u32(s_emb);
            asm volatile(
                "cp.async.bulk.global.shared::cta.bulk_group [%0], [%1], %2;"
                :: "l"(gsh), "r"(ssh), "r"((uint32_t)(BLK * 9 * 4)) : "memory");
            asm volatile(
                "cp.async.bulk.global.shared::cta.bulk_group [%0], [%1], %2;"
                :: "l"(gem), "r"(sem), "r"((uint32_t)(BLK * NB * 4)) : "memory");
            asm volatile("cp.async.bulk.commit_group;" ::: "memory");
            asm volatile("cp.async.bulk.wait_group 0;" ::: "memory");
        }
    } else {
        for (int i = t; i < nval * 9;  i += BLK) out_sh [blockBase * 9  + i] = s_sh [i];
        for (int i = t; i < nval * NB; i += BLK) out_emb[blockBase * NB + i] = s_emb[i];
    }
}

extern "C" void kernel_launch(void* const* d_in, const int* in_sizes, int n_in,
                              void* d_out, int out_size)
{
    const float* pos  = (const float*)d_in[0];
    const float* qpos = (const float*)d_in[1];
    const int*   esrc = (const int*)  d_in[2];
    const int*   edst = (const int*)  d_in[3];

    const int n_pos  = in_sizes[0] / 3;
    const int n_qpos = in_sizes[1] / 3;
    const int E      = in_sizes[2];

    const int n_pad = n_pos + n_qpos;
    pad_tables_kernel<<<(n_pad + 255) / 256, 256>>>(pos, qpos, n_pos, n_qpos);

    const int blocks = (E + BLK - 1) / BLK;
    qsh_kernel<<<blocks, BLK>>>(esrc, edst, (float*)d_out, E);
}